// round 1
// baseline (speedup 1.0000x reference)
#include <cuda_runtime.h>
#include <cstdint>

#define DIM_C    1024
#define NHEADS   16
#define NKV      4
#define GROUP    4
#define HDIM     64
#define BATCH    2
#define SEQ      2048
#define MTOT     (BATCH * SEQ)          // 4096
#define SCALE_F  0.125f                  // 64^-0.5

// -------- scratch (device globals; no runtime allocation) --------
__device__ float g_q[(size_t)MTOT * DIM_C];                 // (B,N,H,D) row-major
__device__ float g_k[(size_t)MTOT * NKV * HDIM];            // (B,N,KV,D)
__device__ float g_v[(size_t)MTOT * NKV * HDIM];
__device__ float g_o[(size_t)MTOT * DIM_C];                 // attention output, (B,N,H,D)

// ============================================================================
// SGEMM: C[M,Nn] = A[M,1024] @ W[1024,Nn] (+ bias). 128x128x8 tile, 8x8/thread.
// ============================================================================
__device__ __forceinline__ void gemm128(const float* __restrict__ A,
                                        const float* __restrict__ W,
                                        const float* __restrict__ bias,
                                        float* __restrict__ C,
                                        const int Nn, const int cb, const int rb,
                                        const bool use_bias) {
    __shared__ float As[8][128];   // transposed A tile: As[k][row]
    __shared__ float Bs[8][128];   // Bs[k][col]
    const int K = 1024;
    const int tid = threadIdx.x;
    const int ty = tid >> 4;            // 0..15
    const int tx = tid & 15;            // 0..15

    const int arow = tid >> 1;          // 0..127
    const int ac   = (tid & 1) << 2;    // 0 or 4
    const int brow = tid >> 5;          // 0..7
    const int bc4  = (tid & 31) << 2;   // 0..124

    const float* Ap = A + (size_t)(rb * 128 + arow) * K + ac;
    const float* Bp = W + (size_t)brow * Nn + cb * 128 + bc4;

    float acc[8][8] = {};

    for (int k0 = 0; k0 < K; k0 += 8) {
        float4 a = *(const float4*)Ap;
        float4 b = *(const float4*)Bp;
        As[ac + 0][arow] = a.x;
        As[ac + 1][arow] = a.y;
        As[ac + 2][arow] = a.z;
        As[ac + 3][arow] = a.w;
        *(float4*)&Bs[brow][bc4] = b;
        __syncthreads();
        #pragma unroll
        for (int kk = 0; kk < 8; kk++) {
            float ra[8], rb_[8];
            *(float4*)&ra[0]  = *(const float4*)&As[kk][ty * 4];
            *(float4*)&ra[4]  = *(const float4*)&As[kk][64 + ty * 4];
            *(float4*)&rb_[0] = *(const float4*)&Bs[kk][tx * 4];
            *(float4*)&rb_[4] = *(const float4*)&Bs[kk][64 + tx * 4];
            #pragma unroll
            for (int i = 0; i < 8; i++)
                #pragma unroll
                for (int j = 0; j < 8; j++)
                    acc[i][j] += ra[i] * rb_[j];
        }
        __syncthreads();
        Ap += 8;
        Bp += (size_t)8 * Nn;
    }

    #pragma unroll
    for (int i = 0; i < 8; i++) {
        int r = rb * 128 + ((i < 4) ? (ty * 4 + i) : (64 + ty * 4 + (i - 4)));
        #pragma unroll
        for (int jh = 0; jh < 2; jh++) {
            int c = cb * 128 + (jh ? (64 + tx * 4) : (tx * 4));
            float4 ov;
            ov.x = acc[i][jh * 4 + 0];
            ov.y = acc[i][jh * 4 + 1];
            ov.z = acc[i][jh * 4 + 2];
            ov.w = acc[i][jh * 4 + 3];
            if (use_bias) {
                ov.x += bias[c + 0];
                ov.y += bias[c + 1];
                ov.z += bias[c + 2];
                ov.w += bias[c + 3];
            }
            *(float4*)&C[(size_t)r * Nn + c] = ov;
        }
    }
}

// Fused QKV projection: blockIdx.x selects which weight/output (8 q, 2 k, 2 v col-blocks)
__global__ void __launch_bounds__(256)
qkv_gemm_kernel(const float* __restrict__ x,
                const float* __restrict__ Wq, const float* __restrict__ Wk,
                const float* __restrict__ Wv,
                float* __restrict__ q, float* __restrict__ k, float* __restrict__ v) {
    const int bc = blockIdx.x;
    const float* W;
    float* C;
    int Nn, cb;
    if (bc < 8)       { W = Wq; C = q; Nn = 1024; cb = bc; }
    else if (bc < 10) { W = Wk; C = k; Nn = 256;  cb = bc - 8; }
    else              { W = Wv; C = v; Nn = 256;  cb = bc - 10; }
    gemm128(x, W, nullptr, C, Nn, cb, blockIdx.y, false);
}

__global__ void __launch_bounds__(256)
out_gemm_kernel(const float* __restrict__ o, const float* __restrict__ Wo,
                const float* __restrict__ bo, float* __restrict__ out) {
    gemm128(o, Wo, bo, out, 1024, blockIdx.x, blockIdx.y, true);
}

// ============================================================================
// Flash attention: one CTA = 64 queries x 1 head. Tiles of 64 keys.
// smem: Q[64][68], K^T[64][68], V[64][68], S[64][68] + m/l/scale[64].
// ============================================================================
#define FLASH_SMEM_FLOATS (4 * 64 * 68 + 3 * 64)
#define FLASH_SMEM_BYTES  (FLASH_SMEM_FLOATS * 4)

__global__ void __launch_bounds__(256)
flash_attn_kernel(const float* __restrict__ q, const float* __restrict__ k,
                  const float* __restrict__ v, float* __restrict__ o) {
    extern __shared__ float sm[];
    float (*Qs)[68]  = (float(*)[68])(sm);
    float (*KsT)[68] = (float(*)[68])(sm + 64 * 68);      // KsT[d][key]
    float (*Vs)[68]  = (float(*)[68])(sm + 2 * 64 * 68);  // Vs[key][d]
    float (*Ss)[68]  = (float(*)[68])(sm + 3 * 64 * 68);  // Ss[q][key]
    float* m_s  = sm + 4 * 64 * 68;
    float* l_s  = m_s + 64;
    float* sc_s = l_s + 64;

    const int tid  = threadIdx.x;
    const int ty   = tid >> 4;    // 0..15
    const int tx   = tid & 15;    // 0..15
    const int head = blockIdx.y;
    const int b    = blockIdx.z;
    const int kvh  = head >> 2;   // head / GROUP
    const int q0   = blockIdx.x * 64;

    // load Q tile (64 x 64), coalesced float4
    #pragma unroll
    for (int t = 0; t < 4; t++) {
        int idx = tid + t * 256;
        int r = idx >> 4, c4 = (idx & 15) << 2;
        float4 val = *(const float4*)&q[((size_t)((b * SEQ + q0 + r) * NHEADS + head)) * HDIM + c4];
        *(float4*)&Qs[r][c4] = val;
    }
    if (tid < 64) { m_s[tid] = -3.0e38f; l_s[tid] = 0.0f; }

    float accO[4][4] = {};
    __syncthreads();

    for (int kt = 0; kt < SEQ / 64; kt++) {
        const int kbase = kt * 64;
        // load K (transposed into KsT) and V (natural layout)
        #pragma unroll
        for (int t = 0; t < 4; t++) {
            int idx = tid + t * 256;
            int r = idx >> 4, c4 = (idx & 15) << 2;
            size_t gi = ((size_t)((b * SEQ + kbase + r) * NKV + kvh)) * HDIM + c4;
            float4 kv4 = *(const float4*)&k[gi];
            KsT[c4 + 0][r] = kv4.x;
            KsT[c4 + 1][r] = kv4.y;
            KsT[c4 + 2][r] = kv4.z;
            KsT[c4 + 3][r] = kv4.w;
            *(float4*)&Vs[r][c4] = *(const float4*)&v[gi];
        }
        __syncthreads();

        // S = Q @ K^T  (4x4 per thread: rows ty*4+i, cols tx*4+j)
        float s[4][4] = {};
        #pragma unroll 8
        for (int d = 0; d < 64; d++) {
            float4 kv4 = *(const float4*)&KsT[d][tx * 4];
            #pragma unroll
            for (int i = 0; i < 4; i++) {
                float qv = Qs[ty * 4 + i][d];
                s[i][0] += qv * kv4.x;
                s[i][1] += qv * kv4.y;
                s[i][2] += qv * kv4.z;
                s[i][3] += qv * kv4.w;
            }
        }
        #pragma unroll
        for (int i = 0; i < 4; i++) {
            float4 sv;
            sv.x = s[i][0] * SCALE_F;
            sv.y = s[i][1] * SCALE_F;
            sv.z = s[i][2] * SCALE_F;
            sv.w = s[i][3] * SCALE_F;
            *(float4*)&Ss[ty * 4 + i][tx * 4] = sv;
        }
        __syncthreads();

        // online softmax: 4 threads per row, 16 cols each
        {
            const int row = tid >> 2;
            const int c0  = (tid & 3) * 16;
            float mx = -3.0e38f;
            #pragma unroll
            for (int j = 0; j < 16; j++) mx = fmaxf(mx, Ss[row][c0 + j]);
            mx = fmaxf(mx, __shfl_xor_sync(0xffffffffu, mx, 1));
            mx = fmaxf(mx, __shfl_xor_sync(0xffffffffu, mx, 2));
            const float m_old = m_s[row];
            const float m_new = fmaxf(m_old, mx);
            float sum = 0.0f;
            #pragma unroll
            for (int j = 0; j < 16; j++) {
                float p = __expf(Ss[row][c0 + j] - m_new);
                Ss[row][c0 + j] = p;
                sum += p;
            }
            sum += __shfl_xor_sync(0xffffffffu, sum, 1);
            sum += __shfl_xor_sync(0xffffffffu, sum, 2);
            if ((tid & 3) == 0) {
                sc_s[row] = __expf(m_old - m_new);
                m_s[row]  = m_new;
                l_s[row]  = l_s[row] * __expf(m_old - m_new) + sum;
            }
        }
        __syncthreads();

        // O = O * scale + P @ V   (rows ty*4+i, dims tx*4+j)
        #pragma unroll
        for (int i = 0; i < 4; i++) {
            float sc = sc_s[ty * 4 + i];
            accO[i][0] *= sc; accO[i][1] *= sc; accO[i][2] *= sc; accO[i][3] *= sc;
        }
        #pragma unroll 8
        for (int kk = 0; kk < 64; kk++) {
            float4 vv = *(const float4*)&Vs[kk][tx * 4];
            #pragma unroll
            for (int i = 0; i < 4; i++) {
                float p = Ss[ty * 4 + i][kk];
                accO[i][0] += p * vv.x;
                accO[i][1] += p * vv.y;
                accO[i][2] += p * vv.z;
                accO[i][3] += p * vv.w;
            }
        }
        __syncthreads();
    }

    // finalize: divide by l, write (B,N,H,D)
    #pragma unroll
    for (int i = 0; i < 4; i++) {
        const int r = ty * 4 + i;
        const float inv = 1.0f / l_s[r];
        float4 ov;
        ov.x = accO[i][0] * inv;
        ov.y = accO[i][1] * inv;
        ov.z = accO[i][2] * inv;
        ov.w = accO[i][3] * inv;
        *(float4*)&o[((size_t)((b * SEQ + q0 + r) * NHEADS + head)) * HDIM + tx * 4] = ov;
    }
}

// ============================================================================
// launcher
// ============================================================================
extern "C" void kernel_launch(void* const* d_in, const int* in_sizes, int n_in,
                              void* d_out, int out_size) {
    (void)in_sizes; (void)n_in; (void)out_size;
    const float* x  = (const float*)d_in[0];
    const float* Wq = (const float*)d_in[1];
    const float* Wk = (const float*)d_in[2];
    const float* Wv = (const float*)d_in[3];
    const float* Wo = (const float*)d_in[4];
    const float* bo = (const float*)d_in[5];
    float* out = (float*)d_out;

    // resolve scratch symbols + smem carveout (non-stream APIs; capture-safe,
    // executed identically on every call)
    float *qp, *kp, *vp, *op;
    cudaGetSymbolAddress((void**)&qp, g_q);
    cudaGetSymbolAddress((void**)&kp, g_k);
    cudaGetSymbolAddress((void**)&vp, g_v);
    cudaGetSymbolAddress((void**)&op, g_o);
    cudaFuncSetAttribute(flash_attn_kernel,
                         cudaFuncAttributeMaxDynamicSharedMemorySize, FLASH_SMEM_BYTES);

    // 1) fused QKV projection: grid (12 col-blocks, 32 row-blocks)
    qkv_gemm_kernel<<<dim3(12, 32), 256>>>(x, Wq, Wk, Wv, qp, kp, vp);

    // 2) flash attention: grid (q-tiles=32, heads=16, batch=2)
    flash_attn_kernel<<<dim3(SEQ / 64, NHEADS, BATCH), 256, FLASH_SMEM_BYTES>>>(qp, kp, vp, op);

    // 3) output projection + bias: grid (8, 32)
    out_gemm_kernel<<<dim3(8, 32), 256>>>(op, Wo, bo, out);
}

// round 3
// speedup vs baseline: 6.4227x; 6.4227x over previous
#include <cuda_runtime.h>
#include <cuda_fp16.h>
#include <cstdint>

#define DIM_C    1024
#define NHEADS   16
#define NKV      4
#define HDIM     64
#define BATCH    2
#define SEQ      2048
#define MTOT     4096
// exp(x*0.125) = 2^(x * 0.125*log2(e))
#define EXP_C    0.18033688011112042f

// ===================== helpers =====================
__device__ __forceinline__ uint32_t smem_u32(const void* p) {
    uint32_t a;
    asm("{ .reg .u64 t; cvta.to.shared.u64 t, %1; cvt.u32.u64 %0, t; }" : "=r"(a) : "l"(p));
    return a;
}
__device__ __forceinline__ void ldsm_x4(uint32_t r[4], uint32_t addr) {
    asm volatile("ldmatrix.sync.aligned.m8n8.x4.shared.b16 {%0,%1,%2,%3}, [%4];"
        : "=r"(r[0]), "=r"(r[1]), "=r"(r[2]), "=r"(r[3]) : "r"(addr));
}
__device__ __forceinline__ void ldsm_x4_t(uint32_t r[4], uint32_t addr) {
    asm volatile("ldmatrix.sync.aligned.m8n8.x4.trans.shared.b16 {%0,%1,%2,%3}, [%4];"
        : "=r"(r[0]), "=r"(r[1]), "=r"(r[2]), "=r"(r[3]) : "r"(addr));
}
__device__ __forceinline__ void mma16816(float c[4], const uint32_t a[4], uint32_t b0, uint32_t b1) {
    asm volatile("mma.sync.aligned.m16n8k16.row.col.f32.f16.f16.f32 "
        "{%0,%1,%2,%3}, {%4,%5,%6,%7}, {%8,%9}, {%0,%1,%2,%3};"
        : "+f"(c[0]), "+f"(c[1]), "+f"(c[2]), "+f"(c[3])
        : "r"(a[0]), "r"(a[1]), "r"(a[2]), "r"(a[3]), "r"(b0), "r"(b1));
}
__device__ __forceinline__ void cp16(uint32_t dst, const void* src) {
    asm volatile("cp.async.ca.shared.global [%0], [%1], 16;" :: "r"(dst), "l"(src));
}
#define CP_COMMIT() asm volatile("cp.async.commit_group;")
#define CP_WAIT1()  asm volatile("cp.async.wait_group 1;")
#define CP_WAIT0()  asm volatile("cp.async.wait_group 0;")

__device__ __forceinline__ float ex2f(float x) {
    float y;
    asm("ex2.approx.ftz.f32 %0, %1;" : "=f"(y) : "f"(x));
    return y;
}
__device__ __forceinline__ uint32_t packh2(float a, float b) {
    __half2 h = __floats2half2_rn(a, b);
    return *reinterpret_cast<uint32_t*>(&h);
}

// ldmatrix fragment addresses for tiles stored as [rows][128B] with SW128 swizzle.
// Non-trans: 4 sub-tiles at (row0 + (t&1)*8, kb + (t>>1)*16B)
__device__ __forceinline__ uint32_t fragA(uint32_t base, int row0, int kb, int lane) {
    int t = lane >> 3, r = lane & 7;
    uint32_t off = (uint32_t)((row0 + ((t & 1) << 3) + r) * 128 + kb + ((t >> 1) << 4));
    return base + (off ^ ((off >> 3) & 0x70));
}
// Trans (V): 4 sub-tiles at (k0 + (t>>1)*8 rows, (d0 + (t&1)*8)*2 bytes)
__device__ __forceinline__ uint32_t fragV(uint32_t base, int k0, int d0, int lane) {
    int t = lane >> 3, r = lane & 7;
    uint32_t off = (uint32_t)((k0 + ((t >> 1) << 3) + r) * 128 + ((d0 + ((t & 1) << 3)) << 1));
    return base + (off ^ ((off >> 3) & 0x70));
}

// -------- scratch (device globals) --------
__device__ __half g_xh[(size_t)MTOT * DIM_C];                // x fp16 [4096][1024]
__device__ __half g_qh[(size_t)BATCH * NHEADS * SEQ * HDIM]; // [B,H,N,D]
__device__ __half g_kh[(size_t)BATCH * NKV * SEQ * HDIM];    // [B,KV,N,D]
__device__ __half g_vh[(size_t)BATCH * NKV * SEQ * HDIM];
__device__ __half g_oh[(size_t)MTOT * DIM_C];                // attn out fp16 [4096][1024]
__device__ __half g_wqT[(size_t)DIM_C * DIM_C];              // W^T [n][k] fp16
__device__ __half g_wkT[(size_t)(NKV * HDIM) * DIM_C];
__device__ __half g_wvT[(size_t)(NKV * HDIM) * DIM_C];
__device__ __half g_woT[(size_t)DIM_C * DIM_C];

// ===================== prepass =====================
__global__ void __launch_bounds__(256)
f32_to_f16_kernel(const float* __restrict__ in, __half* __restrict__ out, int n4) {
    int i = blockIdx.x * blockDim.x + threadIdx.x;
    if (i < n4) {
        float4 v = *(const float4*)(in + (size_t)i * 4);
        *(__half2*)(out + (size_t)i * 4)     = __floats2half2_rn(v.x, v.y);
        *(__half2*)(out + (size_t)i * 4 + 2) = __floats2half2_rn(v.z, v.w);
    }
}

// W [1024][N] fp32 -> WT [N][1024] fp16
__global__ void __launch_bounds__(256)
transpose_w_kernel(const float* __restrict__ W, __half* __restrict__ WT, int N) {
    __shared__ float t[32][33];
    const int n0 = blockIdx.x * 32, k0 = blockIdx.y * 32;
    #pragma unroll
    for (int j = 0; j < 32; j += 8)
        t[threadIdx.y + j][threadIdx.x] = W[(size_t)(k0 + threadIdx.y + j) * N + n0 + threadIdx.x];
    __syncthreads();
    #pragma unroll
    for (int j = 0; j < 32; j += 8)
        WT[(size_t)(n0 + threadIdx.y + j) * DIM_C + k0 + threadIdx.x] =
            __float2half(t[threadIdx.x][threadIdx.y + j]);
}

// ===================== HMMA GEMM core =====================
// C[128,128] += A[128,1024] @ B^T[128,1024]^T, fp16 in / fp32 acc.
// 256 threads, warp grid 2(M)x4(N), warp tile 64x32. cp.async 2-stage, BK=64.
// smem: 2 stages x (A 16KB + B 16KB) = 64KB dynamic.
__device__ __forceinline__ void hgemm_core(const __half* __restrict__ Ab,
                                           const __half* __restrict__ Bb,
                                           float acc[4][4][4], uint32_t sbase) {
    const int tid  = threadIdx.x, lane = tid & 31;
    const int wm   = (tid >> 5) >> 2, wn = (tid >> 5) & 3;
    const int row0 = tid >> 3, c16 = tid & 7;

    auto issue = [&](int kt, int st) {
        uint32_t sA = sbase + st * 32768u, sB = sA + 16384u;
        const __half* a = Ab + kt * 64 + c16 * 8;
        const __half* b = Bb + kt * 64 + c16 * 8;
        #pragma unroll
        for (int i = 0; i < 4; i++) {
            int rr = row0 + i * 32;
            uint32_t off = (uint32_t)(rr * 128 + c16 * 16);
            off ^= (off >> 3) & 0x70;
            cp16(sA + off, a + (size_t)rr * DIM_C);
            cp16(sB + off, b + (size_t)rr * DIM_C);
        }
    };

    issue(0, 0); CP_COMMIT();
    for (int kt = 0; kt < 16; kt++) {
        const int st = kt & 1;
        if (kt < 15) { issue(kt + 1, st ^ 1); CP_COMMIT(); CP_WAIT1(); }
        else         { CP_WAIT0(); }
        __syncthreads();
        uint32_t sA = sbase + st * 32768u, sB = sA + 16384u;
        #pragma unroll
        for (int ks = 0; ks < 4; ks++) {
            uint32_t af[4][4], bf[2][4];
            #pragma unroll
            for (int mt = 0; mt < 4; mt++)
                ldsm_x4(af[mt], fragA(sA, wm * 64 + mt * 16, ks * 32, lane));
            ldsm_x4(bf[0], fragA(sB, wn * 32,      ks * 32, lane));
            ldsm_x4(bf[1], fragA(sB, wn * 32 + 16, ks * 32, lane));
            #pragma unroll
            for (int mt = 0; mt < 4; mt++) {
                mma16816(acc[mt][0], af[mt], bf[0][0], bf[0][2]);
                mma16816(acc[mt][1], af[mt], bf[0][1], bf[0][3]);
                mma16816(acc[mt][2], af[mt], bf[1][0], bf[1][2]);
                mma16816(acc[mt][3], af[mt], bf[1][1], bf[1][3]);
            }
        }
        __syncthreads();
    }
}

// QKV GEMM: scatters fp16 results into head-major q/k/v
__global__ void __launch_bounds__(256)
qkv_mma_kernel(const __half* __restrict__ xh,
               const __half* __restrict__ wqT, const __half* __restrict__ wkT,
               const __half* __restrict__ wvT,
               __half* __restrict__ qh, __half* __restrict__ kh, __half* __restrict__ vh) {
    extern __shared__ char dsm[];
    const int cb = blockIdx.x, rb = blockIdx.y;
    const __half* Bb = (cb < 8)  ? wqT + (size_t)cb * 128 * DIM_C
                     : (cb < 10) ? wkT + (size_t)(cb - 8) * 128 * DIM_C
                                 : wvT + (size_t)(cb - 10) * 128 * DIM_C;
    float acc[4][4][4] = {};
    hgemm_core(xh + (size_t)rb * 128 * DIM_C, Bb, acc, smem_u32(dsm));

    const int lane = threadIdx.x & 31, wid = threadIdx.x >> 5;
    const int wm = wid >> 2, wn = wid & 3;
    #pragma unroll
    for (int mt = 0; mt < 4; mt++) {
        const int r0 = rb * 128 + wm * 64 + mt * 16 + (lane >> 2);
        const int bb = r0 >> 11, nn = r0 & 2047;
        #pragma unroll
        for (int nt = 0; nt < 4; nt++) {
            const int gc = cb * 128 + wn * 32 + nt * 8 + (lane & 3) * 2;
            __half* base;
            int loc, nhd;
            if (gc < 1024)      { base = qh; loc = gc;        nhd = NHEADS; }
            else if (gc < 1280) { base = kh; loc = gc - 1024; nhd = NKV; }
            else                { base = vh; loc = gc - 1280; nhd = NKV; }
            const int hh = loc >> 6, dd = loc & 63;
            const size_t o0 = (((size_t)bb * nhd + hh) * SEQ + nn) * HDIM + dd;
            *(__half2*)(base + o0)             = __floats2half2_rn(acc[mt][nt][0], acc[mt][nt][1]);
            *(__half2*)(base + o0 + 8 * HDIM)  = __floats2half2_rn(acc[mt][nt][2], acc[mt][nt][3]);
        }
    }
}

// Output GEMM + bias, fp32 result
__global__ void __launch_bounds__(256)
out_mma_kernel(const __half* __restrict__ oh, const __half* __restrict__ woT,
               const float* __restrict__ bias, float* __restrict__ out) {
    extern __shared__ char dsm[];
    const int cb = blockIdx.x, rb = blockIdx.y;
    float acc[4][4][4] = {};
    hgemm_core(oh + (size_t)rb * 128 * DIM_C, woT + (size_t)cb * 128 * DIM_C, acc, smem_u32(dsm));

    const int lane = threadIdx.x & 31, wid = threadIdx.x >> 5;
    const int wm = wid >> 2, wn = wid & 3;
    #pragma unroll
    for (int mt = 0; mt < 4; mt++) {
        const int r0 = rb * 128 + wm * 64 + mt * 16 + (lane >> 2);
        #pragma unroll
        for (int nt = 0; nt < 4; nt++) {
            const int gc = cb * 128 + wn * 32 + nt * 8 + (lane & 3) * 2;
            const float b0 = bias[gc], b1 = bias[gc + 1];
            float2 v0 = { acc[mt][nt][0] + b0, acc[mt][nt][1] + b1 };
            float2 v1 = { acc[mt][nt][2] + b0, acc[mt][nt][3] + b1 };
            *(float2*)&out[(size_t)r0 * DIM_C + gc]       = v0;
            *(float2*)&out[(size_t)(r0 + 8) * DIM_C + gc] = v1;
        }
    }
}

// ===================== HMMA flash attention =====================
// CTA: 128 queries x 1 head. 8 warps: warp w owns queries w*16..+16.
// Key tiles of 64. smem: Q 16KB + 2 stages x (K 8KB + V 8KB) = 48KB static.
__global__ void __launch_bounds__(256)
attn_mma_kernel(const __half* __restrict__ qh, const __half* __restrict__ kh,
                const __half* __restrict__ vh, __half* __restrict__ oh) {
    __shared__ char sm[49152];
    const uint32_t sb = smem_u32(sm);
    const int tid = threadIdx.x, lane = tid & 31, wid = tid >> 5;
    const int b = blockIdx.z, h = blockIdx.y, q0 = blockIdx.x * 128;
    const __half* Qg = qh + (((size_t)b * NHEADS + h) * SEQ + q0) * HDIM;
    const __half* Kg = kh + (((size_t)b * NKV + (h >> 2)) * SEQ) * HDIM;
    const __half* Vg = vh + (((size_t)b * NKV + (h >> 2)) * SEQ) * HDIM;

    // Q tile 128x64 -> smem (swizzled)
    #pragma unroll
    for (int i = 0; i < 4; i++) {
        const int ch = tid + i * 256;
        const int rr = ch >> 3, c16 = ch & 7;
        uint32_t off = (uint32_t)(rr * 128 + c16 * 16);
        off ^= (off >> 3) & 0x70;
        *(uint4*)(sm + off) = *(const uint4*)(Qg + (size_t)rr * HDIM + c16 * 8);
    }

    const int rr0 = tid >> 3, cc16 = tid & 7;
    auto issueKV = [&](int kt, int st) {
        const uint32_t sK = sb + 16384u + st * 16384u, sV = sK + 8192u;
        const __half* ks = Kg + (size_t)kt * 64 * HDIM;
        const __half* vs = Vg + (size_t)kt * 64 * HDIM;
        #pragma unroll
        for (int i = 0; i < 2; i++) {
            const int rr = rr0 + i * 32;
            uint32_t off = (uint32_t)(rr * 128 + cc16 * 16);
            off ^= (off >> 3) & 0x70;
            cp16(sK + off, ks + (size_t)rr * HDIM + cc16 * 8);
            cp16(sV + off, vs + (size_t)rr * HDIM + cc16 * 8);
        }
    };
    issueKV(0, 0); CP_COMMIT();
    __syncthreads();

    // Q fragments (persistent)
    uint32_t qf[4][4];
    #pragma unroll
    for (int ks = 0; ks < 4; ks++) ldsm_x4(qf[ks], fragA(sb, wid * 16, ks * 32, lane));

    float m0 = -1e30f, m1 = -1e30f, l0 = 0.f, l1 = 0.f;
    float oacc[8][4] = {};

    for (int kt = 0; kt < SEQ / 64; kt++) {
        const int st = kt & 1;
        if (kt < SEQ / 64 - 1) { issueKV(kt + 1, st ^ 1); CP_COMMIT(); CP_WAIT1(); }
        else                   { CP_WAIT0(); }
        __syncthreads();
        const uint32_t sK = sb + 16384u + st * 16384u, sV = sK + 8192u;

        // S = Q @ K^T   (K natural [key][d] layout == col-major B operand)
        float sacc[8][4] = {};
        #pragma unroll
        for (int np = 0; np < 4; np++) {
            #pragma unroll
            for (int ks = 0; ks < 4; ks++) {
                uint32_t bf[4];
                ldsm_x4(bf, fragA(sK, np * 16, ks * 32, lane));
                mma16816(sacc[np * 2],     qf[ks], bf[0], bf[2]);
                mma16816(sacc[np * 2 + 1], qf[ks], bf[1], bf[3]);
            }
        }

        // online softmax (rows: r0=lane/4, r1=lane/4+8)
        float mx0 = -1e30f, mx1 = -1e30f;
        #pragma unroll
        for (int nt = 0; nt < 8; nt++) {
            mx0 = fmaxf(mx0, fmaxf(sacc[nt][0], sacc[nt][1]));
            mx1 = fmaxf(mx1, fmaxf(sacc[nt][2], sacc[nt][3]));
        }
        mx0 = fmaxf(mx0, __shfl_xor_sync(0xffffffffu, mx0, 1));
        mx0 = fmaxf(mx0, __shfl_xor_sync(0xffffffffu, mx0, 2));
        mx1 = fmaxf(mx1, __shfl_xor_sync(0xffffffffu, mx1, 1));
        mx1 = fmaxf(mx1, __shfl_xor_sync(0xffffffffu, mx1, 2));
        const float mn0 = fmaxf(m0, mx0), mn1 = fmaxf(m1, mx1);
        const float rf0 = ex2f((m0 - mn0) * EXP_C), rf1 = ex2f((m1 - mn1) * EXP_C);
        m0 = mn0; m1 = mn1;

        uint32_t pf[4][4];
        float s0 = 0.f, s1 = 0.f;
        #pragma unroll
        for (int j = 0; j < 4; j++) {
            const float p00 = ex2f((sacc[2 * j][0] - m0) * EXP_C);
            const float p01 = ex2f((sacc[2 * j][1] - m0) * EXP_C);
            const float p10 = ex2f((sacc[2 * j][2] - m1) * EXP_C);
            const float p11 = ex2f((sacc[2 * j][3] - m1) * EXP_C);
            const float q00 = ex2f((sacc[2 * j + 1][0] - m0) * EXP_C);
            const float q01 = ex2f((sacc[2 * j + 1][1] - m0) * EXP_C);
            const float q10 = ex2f((sacc[2 * j + 1][2] - m1) * EXP_C);
            const float q11 = ex2f((sacc[2 * j + 1][3] - m1) * EXP_C);
            pf[j][0] = packh2(p00, p01);   // row0, k 0-7 of chunk j
            pf[j][1] = packh2(p10, p11);   // row1, k 0-7
            pf[j][2] = packh2(q00, q01);   // row0, k 8-15
            pf[j][3] = packh2(q10, q11);   // row1, k 8-15
            s0 += p00 + p01 + q00 + q01;
            s1 += p10 + p11 + q10 + q11;
        }
        s0 += __shfl_xor_sync(0xffffffffu, s0, 1);
        s0 += __shfl_xor_sync(0xffffffffu, s0, 2);
        s1 += __shfl_xor_sync(0xffffffffu, s1, 1);
        s1 += __shfl_xor_sync(0xffffffffu, s1, 2);
        l0 = l0 * rf0 + s0;
        l1 = l1 * rf1 + s1;
        #pragma unroll
        for (int dt = 0; dt < 8; dt++) {
            oacc[dt][0] *= rf0; oacc[dt][1] *= rf0;
            oacc[dt][2] *= rf1; oacc[dt][3] *= rf1;
        }

        // O += P @ V   (V row-major [key][d] -> ldmatrix.trans)
        #pragma unroll
        for (int dp = 0; dp < 4; dp++) {
            #pragma unroll
            for (int j = 0; j < 4; j++) {
                uint32_t vf[4];
                ldsm_x4_t(vf, fragV(sV, j * 16, dp * 16, lane));
                mma16816(oacc[dp * 2],     pf[j], vf[0], vf[2]);
                mma16816(oacc[dp * 2 + 1], pf[j], vf[1], vf[3]);
            }
        }
        __syncthreads();
    }

    // epilogue: divide by l, write fp16 token-major [B,N,H,D]
    const float il0 = 1.f / l0, il1 = 1.f / l1;
    const int r0 = q0 + wid * 16 + (lane >> 2);
    __half* O0 = oh + (((size_t)b * SEQ + r0) * NHEADS + h) * HDIM;
    __half* O1 = O0 + (size_t)8 * NHEADS * HDIM;
    #pragma unroll
    for (int dt = 0; dt < 8; dt++) {
        const int d = dt * 8 + (lane & 3) * 2;
        *(__half2*)(O0 + d) = __floats2half2_rn(oacc[dt][0] * il0, oacc[dt][1] * il0);
        *(__half2*)(O1 + d) = __floats2half2_rn(oacc[dt][2] * il1, oacc[dt][3] * il1);
    }
}

// ===================== launcher =====================
extern "C" void kernel_launch(void* const* d_in, const int* in_sizes, int n_in,
                              void* d_out, int out_size) {
    (void)in_sizes; (void)n_in; (void)out_size;
    const float* x  = (const float*)d_in[0];
    const float* Wq = (const float*)d_in[1];
    const float* Wk = (const float*)d_in[2];
    const float* Wv = (const float*)d_in[3];
    const float* Wo = (const float*)d_in[4];
    const float* bo = (const float*)d_in[5];
    float* out = (float*)d_out;

    __half *xh, *qhp, *khp, *vhp, *ohp, *wqT, *wkT, *wvT, *woT;
    cudaGetSymbolAddress((void**)&xh,  g_xh);
    cudaGetSymbolAddress((void**)&qhp, g_qh);
    cudaGetSymbolAddress((void**)&khp, g_kh);
    cudaGetSymbolAddress((void**)&vhp, g_vh);
    cudaGetSymbolAddress((void**)&ohp, g_oh);
    cudaGetSymbolAddress((void**)&wqT, g_wqT);
    cudaGetSymbolAddress((void**)&wkT, g_wkT);
    cudaGetSymbolAddress((void**)&wvT, g_wvT);
    cudaGetSymbolAddress((void**)&woT, g_woT);
    cudaFuncSetAttribute(qkv_mma_kernel, cudaFuncAttributeMaxDynamicSharedMemorySize, 65536);
    cudaFuncSetAttribute(out_mma_kernel, cudaFuncAttributeMaxDynamicSharedMemorySize, 65536);

    // 0) prepass: x -> fp16; W -> fp16 transposed [N][K]
    f32_to_f16_kernel<<<(MTOT * DIM_C / 4 + 255) / 256, 256>>>(x, xh, MTOT * DIM_C / 4);
    transpose_w_kernel<<<dim3(DIM_C / 32, DIM_C / 32), dim3(32, 8)>>>(Wq, wqT, DIM_C);
    transpose_w_kernel<<<dim3(NKV * HDIM / 32, DIM_C / 32), dim3(32, 8)>>>(Wk, wkT, NKV * HDIM);
    transpose_w_kernel<<<dim3(NKV * HDIM / 32, DIM_C / 32), dim3(32, 8)>>>(Wv, wvT, NKV * HDIM);
    transpose_w_kernel<<<dim3(DIM_C / 32, DIM_C / 32), dim3(32, 8)>>>(Wo, woT, DIM_C);

    // 1) QKV projection (HMMA), scatter to head-major fp16
    qkv_mma_kernel<<<dim3(12, 32), 256, 65536>>>(xh, wqT, wkT, wvT, qhp, khp, vhp);

    // 2) flash attention (HMMA)
    attn_mma_kernel<<<dim3(SEQ / 128, NHEADS, BATCH), 256>>>(qhp, khp, vhp, ohp);

    // 3) output projection + bias (HMMA), fp32 out
    out_mma_kernel<<<dim3(8, 32), 256, 65536>>>(ohp, woT, bo, out);
}

// round 4
// speedup vs baseline: 7.0573x; 1.0988x over previous
#include <cuda_runtime.h>
#include <cuda_fp16.h>
#include <cstdint>

#define DIM_C    1024
#define NHEADS   16
#define NKV      4
#define HDIM     64
#define BATCH    2
#define SEQ      2048
#define MTOT     4096
// exp(x*0.125) = 2^(x * 0.125*log2(e))
#define EXP_C    0.18033688011112042f

// ===================== helpers =====================
__device__ __forceinline__ uint32_t smem_u32(const void* p) {
    uint32_t a;
    asm("{ .reg .u64 t; cvta.to.shared.u64 t, %1; cvt.u32.u64 %0, t; }" : "=r"(a) : "l"(p));
    return a;
}
__device__ __forceinline__ void ldsm_x4(uint32_t r[4], uint32_t addr) {
    asm volatile("ldmatrix.sync.aligned.m8n8.x4.shared.b16 {%0,%1,%2,%3}, [%4];"
        : "=r"(r[0]), "=r"(r[1]), "=r"(r[2]), "=r"(r[3]) : "r"(addr));
}
__device__ __forceinline__ void ldsm_x4_t(uint32_t r[4], uint32_t addr) {
    asm volatile("ldmatrix.sync.aligned.m8n8.x4.trans.shared.b16 {%0,%1,%2,%3}, [%4];"
        : "=r"(r[0]), "=r"(r[1]), "=r"(r[2]), "=r"(r[3]) : "r"(addr));
}
__device__ __forceinline__ void mma16816(float c[4], const uint32_t a[4], uint32_t b0, uint32_t b1) {
    asm volatile("mma.sync.aligned.m16n8k16.row.col.f32.f16.f16.f32 "
        "{%0,%1,%2,%3}, {%4,%5,%6,%7}, {%8,%9}, {%0,%1,%2,%3};"
        : "+f"(c[0]), "+f"(c[1]), "+f"(c[2]), "+f"(c[3])
        : "r"(a[0]), "r"(a[1]), "r"(a[2]), "r"(a[3]), "r"(b0), "r"(b1));
}
__device__ __forceinline__ void cp16(uint32_t dst, const void* src) {
    asm volatile("cp.async.cg.shared.global [%0], [%1], 16;" :: "r"(dst), "l"(src));
}
#define CP_COMMIT() asm volatile("cp.async.commit_group;")
#define CP_WAIT1()  asm volatile("cp.async.wait_group 1;")

__device__ __forceinline__ float ex2f(float x) {
    float y;
    asm("ex2.approx.ftz.f32 %0, %1;" : "=f"(y) : "f"(x));
    return y;
}
__device__ __forceinline__ uint32_t packh2(float a, float b) {
    __half2 h = __floats2half2_rn(a, b);
    return *reinterpret_cast<uint32_t*>(&h);
}

// ldmatrix fragment addresses for tiles stored as [rows][128B] with SW128 swizzle.
__device__ __forceinline__ uint32_t fragA(uint32_t base, int row0, int kb, int lane) {
    int t = lane >> 3, r = lane & 7;
    uint32_t off = (uint32_t)((row0 + ((t & 1) << 3) + r) * 128 + kb + ((t >> 1) << 4));
    return base + (off ^ ((off >> 3) & 0x70));
}
__device__ __forceinline__ uint32_t fragV(uint32_t base, int k0, int d0, int lane) {
    int t = lane >> 3, r = lane & 7;
    uint32_t off = (uint32_t)((k0 + ((t >> 1) << 3) + r) * 128 + ((d0 + ((t & 1) << 3)) << 1));
    return base + (off ^ ((off >> 3) & 0x70));
}

// -------- scratch (device globals) --------
__device__ __half g_xh[(size_t)MTOT * DIM_C];
__device__ __half g_qh[(size_t)BATCH * NHEADS * SEQ * HDIM]; // [B,H,N,D]
__device__ __half g_kh[(size_t)BATCH * NKV * SEQ * HDIM];    // [B,KV,N,D]
__device__ __half g_vh[(size_t)BATCH * NKV * SEQ * HDIM];
__device__ __half g_oh[(size_t)MTOT * DIM_C];
__device__ __half g_wqT[(size_t)DIM_C * DIM_C];
__device__ __half g_wkT[(size_t)(NKV * HDIM) * DIM_C];
__device__ __half g_wvT[(size_t)(NKV * HDIM) * DIM_C];
__device__ __half g_woT[(size_t)DIM_C * DIM_C];

// ===================== prepass =====================
__global__ void __launch_bounds__(256)
f32_to_f16_kernel(const float* __restrict__ in, __half* __restrict__ out, int n4) {
    int i = blockIdx.x * blockDim.x + threadIdx.x;
    if (i < n4) {
        float4 v = *(const float4*)(in + (size_t)i * 4);
        *(__half2*)(out + (size_t)i * 4)     = __floats2half2_rn(v.x, v.y);
        *(__half2*)(out + (size_t)i * 4 + 2) = __floats2half2_rn(v.z, v.w);
    }
}

// all four weight transposes in one launch; z selects matrix
__global__ void __launch_bounds__(256)
transpose_all_kernel(const float* __restrict__ Wq, const float* __restrict__ Wk,
                     const float* __restrict__ Wv, const float* __restrict__ Wo,
                     __half* __restrict__ wqT, __half* __restrict__ wkT,
                     __half* __restrict__ wvT, __half* __restrict__ woT) {
    __shared__ float t[32][33];
    const int z = blockIdx.z;
    const float* W;
    __half* WT;
    int N;
    if (z == 0)      { W = Wq; WT = wqT; N = 1024; }
    else if (z == 1) { W = Wk; WT = wkT; N = 256; }
    else if (z == 2) { W = Wv; WT = wvT; N = 256; }
    else             { W = Wo; WT = woT; N = 1024; }
    const int n0 = blockIdx.x * 32, k0 = blockIdx.y * 32;
    if (n0 >= N) return;
    #pragma unroll
    for (int j = 0; j < 32; j += 8)
        t[threadIdx.y + j][threadIdx.x] = W[(size_t)(k0 + threadIdx.y + j) * N + n0 + threadIdx.x];
    __syncthreads();
    #pragma unroll
    for (int j = 0; j < 32; j += 8)
        WT[(size_t)(n0 + threadIdx.y + j) * DIM_C + k0 + threadIdx.x] =
            __float2half(t[threadIdx.x][threadIdx.y + j]);
}

// ===================== HMMA GEMM core (3-stage, 1 barrier/iter) =====================
// C[128,128] = A[128,1024] @ B^T[128,1024]^T. 256 thr, warps 2(M)x4(N), tile 64x32.
// smem: 3 stages x (A 16KB + B 16KB) = 96KB dynamic.
#define HG_SMEM_BYTES 98304
__device__ __forceinline__ void hgemm_core(const __half* __restrict__ Ab,
                                           const __half* __restrict__ Bb,
                                           float acc[4][4][4], uint32_t sbase) {
    const int tid  = threadIdx.x, lane = tid & 31;
    const int wm   = (tid >> 5) >> 2, wn = (tid >> 5) & 3;
    const int row0 = tid >> 3, c16 = tid & 7;

    auto issue = [&](int kt) {
        const int st = kt % 3;
        uint32_t sA = sbase + (uint32_t)st * 32768u, sB = sA + 16384u;
        const __half* a = Ab + kt * 64 + c16 * 8;
        const __half* b = Bb + kt * 64 + c16 * 8;
        #pragma unroll
        for (int i = 0; i < 4; i++) {
            int rr = row0 + i * 32;
            uint32_t off = (uint32_t)(rr * 128 + c16 * 16);
            off ^= (off >> 3) & 0x70;
            cp16(sA + off, a + (size_t)rr * DIM_C);
            cp16(sB + off, b + (size_t)rr * DIM_C);
        }
    };

    issue(0); CP_COMMIT();
    issue(1); CP_COMMIT();
    for (int kt = 0; kt < 16; kt++) {
        CP_WAIT1();
        __syncthreads();
        if (kt + 2 < 16) issue(kt + 2);
        CP_COMMIT();
        const int st = kt % 3;
        uint32_t sA = sbase + (uint32_t)st * 32768u, sB = sA + 16384u;
        #pragma unroll
        for (int ks = 0; ks < 4; ks++) {
            uint32_t af[4][4], bf[2][4];
            #pragma unroll
            for (int mt = 0; mt < 4; mt++)
                ldsm_x4(af[mt], fragA(sA, wm * 64 + mt * 16, ks * 32, lane));
            ldsm_x4(bf[0], fragA(sB, wn * 32,      ks * 32, lane));
            ldsm_x4(bf[1], fragA(sB, wn * 32 + 16, ks * 32, lane));
            #pragma unroll
            for (int mt = 0; mt < 4; mt++) {
                mma16816(acc[mt][0], af[mt], bf[0][0], bf[0][2]);
                mma16816(acc[mt][1], af[mt], bf[0][1], bf[0][3]);
                mma16816(acc[mt][2], af[mt], bf[1][0], bf[1][2]);
                mma16816(acc[mt][3], af[mt], bf[1][1], bf[1][3]);
            }
        }
    }
}

__global__ void __launch_bounds__(256)
qkv_mma_kernel(const __half* __restrict__ xh,
               const __half* __restrict__ wqT, const __half* __restrict__ wkT,
               const __half* __restrict__ wvT,
               __half* __restrict__ qh, __half* __restrict__ kh, __half* __restrict__ vh) {
    extern __shared__ char dsm[];
    const int cb = blockIdx.x, rb = blockIdx.y;
    const __half* Bb = (cb < 8)  ? wqT + (size_t)cb * 128 * DIM_C
                     : (cb < 10) ? wkT + (size_t)(cb - 8) * 128 * DIM_C
                                 : wvT + (size_t)(cb - 10) * 128 * DIM_C;
    float acc[4][4][4] = {};
    hgemm_core(xh + (size_t)rb * 128 * DIM_C, Bb, acc, smem_u32(dsm));

    const int lane = threadIdx.x & 31, wid = threadIdx.x >> 5;
    const int wm = wid >> 2, wn = wid & 3;
    #pragma unroll
    for (int mt = 0; mt < 4; mt++) {
        const int r0 = rb * 128 + wm * 64 + mt * 16 + (lane >> 2);
        const int bb = r0 >> 11, nn = r0 & 2047;
        #pragma unroll
        for (int nt = 0; nt < 4; nt++) {
            const int gc = cb * 128 + wn * 32 + nt * 8 + (lane & 3) * 2;
            __half* base;
            int loc, nhd;
            if (gc < 1024)      { base = qh; loc = gc;        nhd = NHEADS; }
            else if (gc < 1280) { base = kh; loc = gc - 1024; nhd = NKV; }
            else                { base = vh; loc = gc - 1280; nhd = NKV; }
            const int hh = loc >> 6, dd = loc & 63;
            const size_t o0 = (((size_t)bb * nhd + hh) * SEQ + nn) * HDIM + dd;
            *(__half2*)(base + o0)            = __floats2half2_rn(acc[mt][nt][0], acc[mt][nt][1]);
            *(__half2*)(base + o0 + 8 * HDIM) = __floats2half2_rn(acc[mt][nt][2], acc[mt][nt][3]);
        }
    }
}

__global__ void __launch_bounds__(256)
out_mma_kernel(const __half* __restrict__ oh, const __half* __restrict__ woT,
               const float* __restrict__ bias, float* __restrict__ out) {
    extern __shared__ char dsm[];
    const int cb = blockIdx.x, rb = blockIdx.y;
    float acc[4][4][4] = {};
    hgemm_core(oh + (size_t)rb * 128 * DIM_C, woT + (size_t)cb * 128 * DIM_C, acc, smem_u32(dsm));

    const int lane = threadIdx.x & 31, wid = threadIdx.x >> 5;
    const int wm = wid >> 2, wn = wid & 3;
    #pragma unroll
    for (int mt = 0; mt < 4; mt++) {
        const int r0 = rb * 128 + wm * 64 + mt * 16 + (lane >> 2);
        #pragma unroll
        for (int nt = 0; nt < 4; nt++) {
            const int gc = cb * 128 + wn * 32 + nt * 8 + (lane & 3) * 2;
            const float b0 = bias[gc], b1 = bias[gc + 1];
            float2 v0 = { acc[mt][nt][0] + b0, acc[mt][nt][1] + b1 };
            float2 v1 = { acc[mt][nt][2] + b0, acc[mt][nt][3] + b1 };
            *(float2*)&out[(size_t)r0 * DIM_C + gc]       = v0;
            *(float2*)&out[(size_t)(r0 + 8) * DIM_C + gc] = v1;
        }
    }
}

// ===================== HMMA flash attention (3-stage, 128-key tiles) =====================
// CTA: 128 queries x 1 head, 8 warps (16 q each). KV stage = 128 keys (K 16KB + V 16KB).
// smem: Q 16KB + 3 x 32KB = 112KB dynamic. One barrier per 128 keys.
#define ATT_SMEM_BYTES 114688
__global__ void __launch_bounds__(256)
attn_mma_kernel(const __half* __restrict__ qh, const __half* __restrict__ kh,
                const __half* __restrict__ vh, __half* __restrict__ oh) {
    extern __shared__ char sm[];
    const uint32_t sb = smem_u32(sm);
    const int tid = threadIdx.x, lane = tid & 31, wid = tid >> 5;
    const int b = blockIdx.z, h = blockIdx.y, q0 = blockIdx.x * 128;
    const __half* Qg = qh + (((size_t)b * NHEADS + h) * SEQ + q0) * HDIM;
    const __half* Kg = kh + (((size_t)b * NKV + (h >> 2)) * SEQ) * HDIM;
    const __half* Vg = vh + (((size_t)b * NKV + (h >> 2)) * SEQ) * HDIM;

    // Q tile 128x64 -> smem (plain stores, swizzled)
    #pragma unroll
    for (int i = 0; i < 4; i++) {
        const int ch = tid + i * 256;
        const int rr = ch >> 3, c16 = ch & 7;
        uint32_t off = (uint32_t)(rr * 128 + c16 * 16);
        off ^= (off >> 3) & 0x70;
        *(uint4*)(sm + off) = *(const uint4*)(Qg + (size_t)rr * HDIM + c16 * 8);
    }

    const int rr0 = tid >> 3, cc16 = tid & 7;
    auto issueKV = [&](int kt) {               // 128-key tile kt
        const int st = kt % 3;
        const uint32_t sK = sb + 16384u + (uint32_t)st * 32768u, sV = sK + 16384u;
        const __half* ks = Kg + (size_t)kt * 128 * HDIM;
        const __half* vs = Vg + (size_t)kt * 128 * HDIM;
        #pragma unroll
        for (int i = 0; i < 4; i++) {
            const int rr = rr0 + i * 32;
            uint32_t off = (uint32_t)(rr * 128 + cc16 * 16);
            off ^= (off >> 3) & 0x70;
            cp16(sK + off, ks + (size_t)rr * HDIM + cc16 * 8);
            cp16(sV + off, vs + (size_t)rr * HDIM + cc16 * 8);
        }
    };
    issueKV(0); CP_COMMIT();
    issueKV(1); CP_COMMIT();
    __syncthreads();                            // Q visible

    uint32_t qf[4][4];
    #pragma unroll
    for (int ks = 0; ks < 4; ks++) ldsm_x4(qf[ks], fragA(sb, wid * 16, ks * 32, lane));

    float m0 = -1e30f, m1 = -1e30f, l0 = 0.f, l1 = 0.f;
    float oacc[8][4] = {};

    for (int kt = 0; kt < SEQ / 128; kt++) {
        CP_WAIT1();
        __syncthreads();
        if (kt + 2 < SEQ / 128) issueKV(kt + 2);
        CP_COMMIT();
        const int st = kt % 3;
        const uint32_t sK = sb + 16384u + (uint32_t)st * 32768u, sV = sK + 16384u;

        #pragma unroll
        for (int half = 0; half < 2; half++) {
            const int koff = half * 64;
            // S = Q @ K^T
            float sacc[8][4] = {};
            #pragma unroll
            for (int np = 0; np < 4; np++) {
                #pragma unroll
                for (int ks = 0; ks < 4; ks++) {
                    uint32_t bf[4];
                    ldsm_x4(bf, fragA(sK, koff + np * 16, ks * 32, lane));
                    mma16816(sacc[np * 2],     qf[ks], bf[0], bf[2]);
                    mma16816(sacc[np * 2 + 1], qf[ks], bf[1], bf[3]);
                }
            }
            // online softmax (rows r0=lane/4, r1=lane/4+8)
            float mx0 = -1e30f, mx1 = -1e30f;
            #pragma unroll
            for (int nt = 0; nt < 8; nt++) {
                mx0 = fmaxf(mx0, fmaxf(sacc[nt][0], sacc[nt][1]));
                mx1 = fmaxf(mx1, fmaxf(sacc[nt][2], sacc[nt][3]));
            }
            mx0 = fmaxf(mx0, __shfl_xor_sync(0xffffffffu, mx0, 1));
            mx0 = fmaxf(mx0, __shfl_xor_sync(0xffffffffu, mx0, 2));
            mx1 = fmaxf(mx1, __shfl_xor_sync(0xffffffffu, mx1, 1));
            mx1 = fmaxf(mx1, __shfl_xor_sync(0xffffffffu, mx1, 2));
            const float mn0 = fmaxf(m0, mx0), mn1 = fmaxf(m1, mx1);
            const float rf0 = ex2f((m0 - mn0) * EXP_C), rf1 = ex2f((m1 - mn1) * EXP_C);
            m0 = mn0; m1 = mn1;

            uint32_t pf[4][4];
            float s0 = 0.f, s1 = 0.f;
            #pragma unroll
            for (int j = 0; j < 4; j++) {
                const float p00 = ex2f((sacc[2 * j][0] - m0) * EXP_C);
                const float p01 = ex2f((sacc[2 * j][1] - m0) * EXP_C);
                const float p10 = ex2f((sacc[2 * j][2] - m1) * EXP_C);
                const float p11 = ex2f((sacc[2 * j][3] - m1) * EXP_C);
                const float q00 = ex2f((sacc[2 * j + 1][0] - m0) * EXP_C);
                const float q01 = ex2f((sacc[2 * j + 1][1] - m0) * EXP_C);
                const float q10 = ex2f((sacc[2 * j + 1][2] - m1) * EXP_C);
                const float q11 = ex2f((sacc[2 * j + 1][3] - m1) * EXP_C);
                pf[j][0] = packh2(p00, p01);
                pf[j][1] = packh2(p10, p11);
                pf[j][2] = packh2(q00, q01);
                pf[j][3] = packh2(q10, q11);
                s0 += p00 + p01 + q00 + q01;
                s1 += p10 + p11 + q10 + q11;
            }
            s0 += __shfl_xor_sync(0xffffffffu, s0, 1);
            s0 += __shfl_xor_sync(0xffffffffu, s0, 2);
            s1 += __shfl_xor_sync(0xffffffffu, s1, 1);
            s1 += __shfl_xor_sync(0xffffffffu, s1, 2);
            l0 = l0 * rf0 + s0;
            l1 = l1 * rf1 + s1;
            #pragma unroll
            for (int dt = 0; dt < 8; dt++) {
                oacc[dt][0] *= rf0; oacc[dt][1] *= rf0;
                oacc[dt][2] *= rf1; oacc[dt][3] *= rf1;
            }
            // O += P @ V
            #pragma unroll
            for (int dp = 0; dp < 4; dp++) {
                #pragma unroll
                for (int j = 0; j < 4; j++) {
                    uint32_t vf[4];
                    ldsm_x4_t(vf, fragV(sV, koff + j * 16, dp * 16, lane));
                    mma16816(oacc[dp * 2],     pf[j], vf[0], vf[2]);
                    mma16816(oacc[dp * 2 + 1], pf[j], vf[1], vf[3]);
                }
            }
        }
    }

    // epilogue: divide by l, write fp16 token-major [B,N,H,D]
    const float il0 = 1.f / l0, il1 = 1.f / l1;
    const int r0 = q0 + wid * 16 + (lane >> 2);
    __half* O0 = oh + (((size_t)b * SEQ + r0) * NHEADS + h) * HDIM;
    __half* O1 = O0 + (size_t)8 * NHEADS * HDIM;
    #pragma unroll
    for (int dt = 0; dt < 8; dt++) {
        const int d = dt * 8 + (lane & 3) * 2;
        *(__half2*)(O0 + d) = __floats2half2_rn(oacc[dt][0] * il0, oacc[dt][1] * il0);
        *(__half2*)(O1 + d) = __floats2half2_rn(oacc[dt][2] * il1, oacc[dt][3] * il1);
    }
}

// ===================== launcher =====================
extern "C" void kernel_launch(void* const* d_in, const int* in_sizes, int n_in,
                              void* d_out, int out_size) {
    (void)in_sizes; (void)n_in; (void)out_size;
    const float* x  = (const float*)d_in[0];
    const float* Wq = (const float*)d_in[1];
    const float* Wk = (const float*)d_in[2];
    const float* Wv = (const float*)d_in[3];
    const float* Wo = (const float*)d_in[4];
    const float* bo = (const float*)d_in[5];
    float* out = (float*)d_out;

    __half *xh, *qhp, *khp, *vhp, *ohp, *wqT, *wkT, *wvT, *woT;
    cudaGetSymbolAddress((void**)&xh,  g_xh);
    cudaGetSymbolAddress((void**)&qhp, g_qh);
    cudaGetSymbolAddress((void**)&khp, g_kh);
    cudaGetSymbolAddress((void**)&vhp, g_vh);
    cudaGetSymbolAddress((void**)&ohp, g_oh);
    cudaGetSymbolAddress((void**)&wqT, g_wqT);
    cudaGetSymbolAddress((void**)&wkT, g_wkT);
    cudaGetSymbolAddress((void**)&wvT, g_wvT);
    cudaGetSymbolAddress((void**)&woT, g_woT);
    cudaFuncSetAttribute(qkv_mma_kernel,  cudaFuncAttributeMaxDynamicSharedMemorySize, HG_SMEM_BYTES);
    cudaFuncSetAttribute(out_mma_kernel,  cudaFuncAttributeMaxDynamicSharedMemorySize, HG_SMEM_BYTES);
    cudaFuncSetAttribute(attn_mma_kernel, cudaFuncAttributeMaxDynamicSharedMemorySize, ATT_SMEM_BYTES);

    // 0) prepass (2 launches)
    f32_to_f16_kernel<<<(MTOT * DIM_C / 4 + 255) / 256, 256>>>(x, xh, MTOT * DIM_C / 4);
    transpose_all_kernel<<<dim3(32, 32, 4), dim3(32, 8)>>>(Wq, Wk, Wv, Wo, wqT, wkT, wvT, woT);

    // 1) QKV projection (HMMA), scatter to head-major fp16
    qkv_mma_kernel<<<dim3(12, 32), 256, HG_SMEM_BYTES>>>(xh, wqT, wkT, wvT, qhp, khp, vhp);

    // 2) flash attention (HMMA)
    attn_mma_kernel<<<dim3(SEQ / 128, NHEADS, BATCH), 256, ATT_SMEM_BYTES>>>(qhp, khp, vhp, ohp);

    // 3) output projection + bias (HMMA), fp32 out
    out_mma_kernel<<<dim3(8, 32), 256, HG_SMEM_BYTES>>>(ohp, woT, bo, out);
}

// round 5
// speedup vs baseline: 7.3345x; 1.0393x over previous
#include <cuda_runtime.h>
#include <cuda_fp16.h>
#include <cstdint>

#define DIM_C    1024
#define NHEADS   16
#define NKV      4
#define HDIM     64
#define BATCH    2
#define SEQ      2048
#define MTOT     4096
// softmax scale folded into Q: q *= 0.125*log2(e)
#define EXP_C    0.18033688011112042f

// ===================== helpers =====================
__device__ __forceinline__ uint32_t smem_u32(const void* p) {
    uint32_t a;
    asm("{ .reg .u64 t; cvta.to.shared.u64 t, %1; cvt.u32.u64 %0, t; }" : "=r"(a) : "l"(p));
    return a;
}
__device__ __forceinline__ void ldsm_x4(uint32_t r[4], uint32_t addr) {
    asm volatile("ldmatrix.sync.aligned.m8n8.x4.shared.b16 {%0,%1,%2,%3}, [%4];"
        : "=r"(r[0]), "=r"(r[1]), "=r"(r[2]), "=r"(r[3]) : "r"(addr));
}
__device__ __forceinline__ void ldsm_x4_t(uint32_t r[4], uint32_t addr) {
    asm volatile("ldmatrix.sync.aligned.m8n8.x4.trans.shared.b16 {%0,%1,%2,%3}, [%4];"
        : "=r"(r[0]), "=r"(r[1]), "=r"(r[2]), "=r"(r[3]) : "r"(addr));
}
__device__ __forceinline__ void mma16816(float c[4], const uint32_t a[4], uint32_t b0, uint32_t b1) {
    asm volatile("mma.sync.aligned.m16n8k16.row.col.f32.f16.f16.f32 "
        "{%0,%1,%2,%3}, {%4,%5,%6,%7}, {%8,%9}, {%0,%1,%2,%3};"
        : "+f"(c[0]), "+f"(c[1]), "+f"(c[2]), "+f"(c[3])
        : "r"(a[0]), "r"(a[1]), "r"(a[2]), "r"(a[3]), "r"(b0), "r"(b1));
}
__device__ __forceinline__ void cp16(uint32_t dst, const void* src) {
    asm volatile("cp.async.cg.shared.global [%0], [%1], 16;" :: "r"(dst), "l"(src));
}
#define CP_COMMIT() asm volatile("cp.async.commit_group;")
#define CP_WAIT1()  asm volatile("cp.async.wait_group 1;")

__device__ __forceinline__ float ex2f(float x) {
    float y;
    asm("ex2.approx.ftz.f32 %0, %1;" : "=f"(y) : "f"(x));
    return y;
}
__device__ __forceinline__ uint32_t packh2(float a, float b) {
    __half2 h = __floats2half2_rn(a, b);
    return *reinterpret_cast<uint32_t*>(&h);
}

// ldmatrix fragment addresses for tiles stored as [rows][128B] with SW128 swizzle.
__device__ __forceinline__ uint32_t fragA(uint32_t base, int row0, int kb, int lane) {
    int t = lane >> 3, r = lane & 7;
    uint32_t off = (uint32_t)((row0 + ((t & 1) << 3) + r) * 128 + kb + ((t >> 1) << 4));
    return base + (off ^ ((off >> 3) & 0x70));
}
__device__ __forceinline__ uint32_t fragV(uint32_t base, int k0, int d0, int lane) {
    int t = lane >> 3, r = lane & 7;
    uint32_t off = (uint32_t)((k0 + ((t >> 1) << 3) + r) * 128 + ((d0 + ((t & 1) << 3)) << 1));
    return base + (off ^ ((off >> 3) & 0x70));
}

// -------- scratch (device globals) --------
__device__ __half g_xh[(size_t)MTOT * DIM_C];
__device__ __half g_qh[(size_t)BATCH * NHEADS * SEQ * HDIM]; // [B,H,N,D] (pre-scaled)
__device__ __half g_kh[(size_t)BATCH * NKV * SEQ * HDIM];    // [B,KV,N,D]
__device__ __half g_vh[(size_t)BATCH * NKV * SEQ * HDIM];
__device__ __half g_oh[(size_t)MTOT * DIM_C];
__device__ __half g_wqT[(size_t)DIM_C * DIM_C];
__device__ __half g_wkT[(size_t)(NKV * HDIM) * DIM_C];
__device__ __half g_wvT[(size_t)(NKV * HDIM) * DIM_C];
__device__ __half g_woT[(size_t)DIM_C * DIM_C];

// ===================== prepass =====================
__global__ void __launch_bounds__(256)
f32_to_f16_kernel(const float* __restrict__ in, __half* __restrict__ out, int n4) {
    int i = blockIdx.x * blockDim.x + threadIdx.x;
    if (i < n4) {
        float4 v = *(const float4*)(in + (size_t)i * 4);
        *(__half2*)(out + (size_t)i * 4)     = __floats2half2_rn(v.x, v.y);
        *(__half2*)(out + (size_t)i * 4 + 2) = __floats2half2_rn(v.z, v.w);
    }
}

__global__ void __launch_bounds__(256)
transpose_all_kernel(const float* __restrict__ Wq, const float* __restrict__ Wk,
                     const float* __restrict__ Wv, const float* __restrict__ Wo,
                     __half* __restrict__ wqT, __half* __restrict__ wkT,
                     __half* __restrict__ wvT, __half* __restrict__ woT) {
    __shared__ float t[32][33];
    const int z = blockIdx.z;
    const float* W;
    __half* WT;
    int N;
    if (z == 0)      { W = Wq; WT = wqT; N = 1024; }
    else if (z == 1) { W = Wk; WT = wkT; N = 256; }
    else if (z == 2) { W = Wv; WT = wvT; N = 256; }
    else             { W = Wo; WT = woT; N = 1024; }
    const int n0 = blockIdx.x * 32, k0 = blockIdx.y * 32;
    if (n0 >= N) return;
    #pragma unroll
    for (int j = 0; j < 32; j += 8)
        t[threadIdx.y + j][threadIdx.x] = W[(size_t)(k0 + threadIdx.y + j) * N + n0 + threadIdx.x];
    __syncthreads();
    #pragma unroll
    for (int j = 0; j < 32; j += 8)
        WT[(size_t)(n0 + threadIdx.y + j) * DIM_C + k0 + threadIdx.x] =
            __float2half(t[threadIdx.x][threadIdx.y + j]);
}

// ===================== HMMA GEMM core (3-stage, 1 barrier/iter) =====================
#define HG_SMEM_BYTES 98304
__device__ __forceinline__ void hgemm_core(const __half* __restrict__ Ab,
                                           const __half* __restrict__ Bb,
                                           float acc[4][4][4], uint32_t sbase) {
    const int tid  = threadIdx.x, lane = tid & 31;
    const int wm   = (tid >> 5) >> 2, wn = (tid >> 5) & 3;
    const int row0 = tid >> 3, c16 = tid & 7;

    auto issue = [&](int kt) {
        const int st = kt % 3;
        uint32_t sA = sbase + (uint32_t)st * 32768u, sB = sA + 16384u;
        const __half* a = Ab + kt * 64 + c16 * 8;
        const __half* b = Bb + kt * 64 + c16 * 8;
        #pragma unroll
        for (int i = 0; i < 4; i++) {
            int rr = row0 + i * 32;
            uint32_t off = (uint32_t)(rr * 128 + c16 * 16);
            off ^= (off >> 3) & 0x70;
            cp16(sA + off, a + (size_t)rr * DIM_C);
            cp16(sB + off, b + (size_t)rr * DIM_C);
        }
    };

    issue(0); CP_COMMIT();
    issue(1); CP_COMMIT();
    for (int kt = 0; kt < 16; kt++) {
        CP_WAIT1();
        __syncthreads();
        if (kt + 2 < 16) issue(kt + 2);
        CP_COMMIT();
        const int st = kt % 3;
        uint32_t sA = sbase + (uint32_t)st * 32768u, sB = sA + 16384u;
        #pragma unroll
        for (int ks = 0; ks < 4; ks++) {
            uint32_t af[4][4], bf[2][4];
            #pragma unroll
            for (int mt = 0; mt < 4; mt++)
                ldsm_x4(af[mt], fragA(sA, wm * 64 + mt * 16, ks * 32, lane));
            ldsm_x4(bf[0], fragA(sB, wn * 32,      ks * 32, lane));
            ldsm_x4(bf[1], fragA(sB, wn * 32 + 16, ks * 32, lane));
            #pragma unroll
            for (int mt = 0; mt < 4; mt++) {
                mma16816(acc[mt][0], af[mt], bf[0][0], bf[0][2]);
                mma16816(acc[mt][1], af[mt], bf[0][1], bf[0][3]);
                mma16816(acc[mt][2], af[mt], bf[1][0], bf[1][2]);
                mma16816(acc[mt][3], af[mt], bf[1][1], bf[1][3]);
            }
        }
    }
}

__global__ void __launch_bounds__(256)
qkv_mma_kernel(const __half* __restrict__ xh,
               const __half* __restrict__ wqT, const __half* __restrict__ wkT,
               const __half* __restrict__ wvT,
               __half* __restrict__ qh, __half* __restrict__ kh, __half* __restrict__ vh) {
    extern __shared__ char dsm[];
    const int cb = blockIdx.x, rb = blockIdx.y;
    const __half* Bb = (cb < 8)  ? wqT + (size_t)cb * 128 * DIM_C
                     : (cb < 10) ? wkT + (size_t)(cb - 8) * 128 * DIM_C
                                 : wvT + (size_t)(cb - 10) * 128 * DIM_C;
    float acc[4][4][4] = {};
    hgemm_core(xh + (size_t)rb * 128 * DIM_C, Bb, acc, smem_u32(dsm));

    const int lane = threadIdx.x & 31, wid = threadIdx.x >> 5;
    const int wm = wid >> 2, wn = wid & 3;
    #pragma unroll
    for (int mt = 0; mt < 4; mt++) {
        const int r0 = rb * 128 + wm * 64 + mt * 16 + (lane >> 2);
        const int bb = r0 >> 11, nn = r0 & 2047;
        #pragma unroll
        for (int nt = 0; nt < 4; nt++) {
            const int gc = cb * 128 + wn * 32 + nt * 8 + (lane & 3) * 2;
            __half* base;
            int loc, nhd;
            float sc;
            if (gc < 1024)      { base = qh; loc = gc;        nhd = NHEADS; sc = EXP_C; }
            else if (gc < 1280) { base = kh; loc = gc - 1024; nhd = NKV;    sc = 1.0f; }
            else                { base = vh; loc = gc - 1280; nhd = NKV;    sc = 1.0f; }
            const int hh = loc >> 6, dd = loc & 63;
            const size_t o0 = (((size_t)bb * nhd + hh) * SEQ + nn) * HDIM + dd;
            *(__half2*)(base + o0)            = __floats2half2_rn(acc[mt][nt][0] * sc, acc[mt][nt][1] * sc);
            *(__half2*)(base + o0 + 8 * HDIM) = __floats2half2_rn(acc[mt][nt][2] * sc, acc[mt][nt][3] * sc);
        }
    }
}

__global__ void __launch_bounds__(256)
out_mma_kernel(const __half* __restrict__ oh, const __half* __restrict__ woT,
               const float* __restrict__ bias, float* __restrict__ out) {
    extern __shared__ char dsm[];
    const int cb = blockIdx.x, rb = blockIdx.y;
    float acc[4][4][4] = {};
    hgemm_core(oh + (size_t)rb * 128 * DIM_C, woT + (size_t)cb * 128 * DIM_C, acc, smem_u32(dsm));

    const int lane = threadIdx.x & 31, wid = threadIdx.x >> 5;
    const int wm = wid >> 2, wn = wid & 3;
    #pragma unroll
    for (int mt = 0; mt < 4; mt++) {
        const int r0 = rb * 128 + wm * 64 + mt * 16 + (lane >> 2);
        #pragma unroll
        for (int nt = 0; nt < 4; nt++) {
            const int gc = cb * 128 + wn * 32 + nt * 8 + (lane & 3) * 2;
            const float b0 = bias[gc], b1 = bias[gc + 1];
            float2 v0 = { acc[mt][nt][0] + b0, acc[mt][nt][1] + b1 };
            float2 v1 = { acc[mt][nt][2] + b0, acc[mt][nt][3] + b1 };
            *(float2*)&out[(size_t)r0 * DIM_C + gc]       = v0;
            *(float2*)&out[(size_t)(r0 + 8) * DIM_C + gc] = v1;
        }
    }
}

// ===================== HMMA flash attention =====================
// CTA: 256 queries x 1 head, 512 threads / 16 warps (16 q each).
// KV stage = 128 keys (K 16KB + V 16KB), 3 stages. smem: Q 32KB + 96KB = 128KB.
#define ATT_SMEM_BYTES 131072
__global__ void __launch_bounds__(512)
attn_mma_kernel(const __half* __restrict__ qh, const __half* __restrict__ kh,
                const __half* __restrict__ vh, __half* __restrict__ oh) {
    extern __shared__ char sm[];
    const uint32_t sb = smem_u32(sm);
    const int tid = threadIdx.x, lane = tid & 31, wid = tid >> 5;
    const int b = blockIdx.z, h = blockIdx.y, q0 = blockIdx.x * 256;
    const __half* Qg = qh + (((size_t)b * NHEADS + h) * SEQ + q0) * HDIM;
    const __half* Kg = kh + (((size_t)b * NKV + (h >> 2)) * SEQ) * HDIM;
    const __half* Vg = vh + (((size_t)b * NKV + (h >> 2)) * SEQ) * HDIM;

    // Q tile 256x64 -> smem (swizzled)
    #pragma unroll
    for (int i = 0; i < 4; i++) {
        const int ch = tid + i * 512;
        const int rr = ch >> 3, c16 = ch & 7;
        uint32_t off = (uint32_t)(rr * 128 + c16 * 16);
        off ^= (off >> 3) & 0x70;
        *(uint4*)(sm + off) = *(const uint4*)(Qg + (size_t)rr * HDIM + c16 * 8);
    }

    const int rr0 = tid >> 3, cc16 = tid & 7;
    auto issueKV = [&](int kt) {               // 128-key tile kt
        const int st = kt % 3;
        const uint32_t sK = sb + 32768u + (uint32_t)st * 32768u, sV = sK + 16384u;
        const __half* ks = Kg + (size_t)kt * 128 * HDIM;
        const __half* vs = Vg + (size_t)kt * 128 * HDIM;
        #pragma unroll
        for (int i = 0; i < 2; i++) {
            const int rr = rr0 + i * 64;
            uint32_t off = (uint32_t)(rr * 128 + cc16 * 16);
            off ^= (off >> 3) & 0x70;
            cp16(sK + off, ks + (size_t)rr * HDIM + cc16 * 8);
            cp16(sV + off, vs + (size_t)rr * HDIM + cc16 * 8);
        }
    };
    issueKV(0); CP_COMMIT();
    issueKV(1); CP_COMMIT();
    __syncthreads();                            // Q visible

    uint32_t qf[4][4];
    #pragma unroll
    for (int ks = 0; ks < 4; ks++) ldsm_x4(qf[ks], fragA(sb, wid * 16, ks * 32, lane));

    float m0 = -1e30f, m1 = -1e30f, l0 = 0.f, l1 = 0.f;   // l: per-thread partials
    float oacc[8][4] = {};

    for (int kt = 0; kt < SEQ / 128; kt++) {
        CP_WAIT1();
        __syncthreads();
        if (kt + 2 < SEQ / 128) issueKV(kt + 2);
        CP_COMMIT();
        const int st = kt % 3;
        const uint32_t sK = sb + 32768u + (uint32_t)st * 32768u, sV = sK + 16384u;

        #pragma unroll
        for (int half = 0; half < 2; half++) {
            const int koff = half * 64;
            // S = Qs @ K^T  (Q pre-scaled; S already in log2 domain)
            float sacc[8][4] = {};
            #pragma unroll
            for (int np = 0; np < 4; np++) {
                #pragma unroll
                for (int ks = 0; ks < 4; ks++) {
                    uint32_t bf[4];
                    ldsm_x4(bf, fragA(sK, koff + np * 16, ks * 32, lane));
                    mma16816(sacc[np * 2],     qf[ks], bf[0], bf[2]);
                    mma16816(sacc[np * 2 + 1], qf[ks], bf[1], bf[3]);
                }
            }
            // online softmax (rows r0=lane/4, r1=lane/4+8)
            float mx0 = -1e30f, mx1 = -1e30f;
            #pragma unroll
            for (int nt = 0; nt < 8; nt++) {
                mx0 = fmaxf(mx0, fmaxf(sacc[nt][0], sacc[nt][1]));
                mx1 = fmaxf(mx1, fmaxf(sacc[nt][2], sacc[nt][3]));
            }
            mx0 = fmaxf(mx0, __shfl_xor_sync(0xffffffffu, mx0, 1));
            mx0 = fmaxf(mx0, __shfl_xor_sync(0xffffffffu, mx0, 2));
            mx1 = fmaxf(mx1, __shfl_xor_sync(0xffffffffu, mx1, 1));
            mx1 = fmaxf(mx1, __shfl_xor_sync(0xffffffffu, mx1, 2));
            const float mn0 = fmaxf(m0, mx0), mn1 = fmaxf(m1, mx1);
            const float rf0 = ex2f(m0 - mn0), rf1 = ex2f(m1 - mn1);
            m0 = mn0; m1 = mn1;

            uint32_t pf[4][4];
            float s0 = 0.f, s1 = 0.f;
            #pragma unroll
            for (int j = 0; j < 4; j++) {
                const float p00 = ex2f(sacc[2 * j][0] - m0);
                const float p01 = ex2f(sacc[2 * j][1] - m0);
                const float p10 = ex2f(sacc[2 * j][2] - m1);
                const float p11 = ex2f(sacc[2 * j][3] - m1);
                const float q00 = ex2f(sacc[2 * j + 1][0] - m0);
                const float q01 = ex2f(sacc[2 * j + 1][1] - m0);
                const float q10 = ex2f(sacc[2 * j + 1][2] - m1);
                const float q11 = ex2f(sacc[2 * j + 1][3] - m1);
                pf[j][0] = packh2(p00, p01);
                pf[j][1] = packh2(p10, p11);
                pf[j][2] = packh2(q00, q01);
                pf[j][3] = packh2(q10, q11);
                s0 += p00 + p01 + q00 + q01;
                s1 += p10 + p11 + q10 + q11;
            }
            l0 = l0 * rf0 + s0;       // per-thread partial (reduced at end)
            l1 = l1 * rf1 + s1;
            #pragma unroll
            for (int dt = 0; dt < 8; dt++) {
                oacc[dt][0] *= rf0; oacc[dt][1] *= rf0;
                oacc[dt][2] *= rf1; oacc[dt][3] *= rf1;
            }
            // O += P @ V
            #pragma unroll
            for (int dp = 0; dp < 4; dp++) {
                #pragma unroll
                for (int j = 0; j < 4; j++) {
                    uint32_t vf[4];
                    ldsm_x4_t(vf, fragV(sV, koff + j * 16, dp * 16, lane));
                    mma16816(oacc[dp * 2],     pf[j], vf[0], vf[2]);
                    mma16816(oacc[dp * 2 + 1], pf[j], vf[1], vf[3]);
                }
            }
        }
    }

    // final l reduction, then epilogue
    l0 += __shfl_xor_sync(0xffffffffu, l0, 1);
    l0 += __shfl_xor_sync(0xffffffffu, l0, 2);
    l1 += __shfl_xor_sync(0xffffffffu, l1, 1);
    l1 += __shfl_xor_sync(0xffffffffu, l1, 2);
    const float il0 = 1.f / l0, il1 = 1.f / l1;
    const int r0 = q0 + wid * 16 + (lane >> 2);
    __half* O0 = oh + (((size_t)b * SEQ + r0) * NHEADS + h) * HDIM;
    __half* O1 = O0 + (size_t)8 * NHEADS * HDIM;
    #pragma unroll
    for (int dt = 0; dt < 8; dt++) {
        const int d = dt * 8 + (lane & 3) * 2;
        *(__half2*)(O0 + d) = __floats2half2_rn(oacc[dt][0] * il0, oacc[dt][1] * il0);
        *(__half2*)(O1 + d) = __floats2half2_rn(oacc[dt][2] * il1, oacc[dt][3] * il1);
    }
}

// ===================== launcher =====================
extern "C" void kernel_launch(void* const* d_in, const int* in_sizes, int n_in,
                              void* d_out, int out_size) {
    (void)in_sizes; (void)n_in; (void)out_size;
    const float* x  = (const float*)d_in[0];
    const float* Wq = (const float*)d_in[1];
    const float* Wk = (const float*)d_in[2];
    const float* Wv = (const float*)d_in[3];
    const float* Wo = (const float*)d_in[4];
    const float* bo = (const float*)d_in[5];
    float* out = (float*)d_out;

    __half *xh, *qhp, *khp, *vhp, *ohp, *wqT, *wkT, *wvT, *woT;
    cudaGetSymbolAddress((void**)&xh,  g_xh);
    cudaGetSymbolAddress((void**)&qhp, g_qh);
    cudaGetSymbolAddress((void**)&khp, g_kh);
    cudaGetSymbolAddress((void**)&vhp, g_vh);
    cudaGetSymbolAddress((void**)&ohp, g_oh);
    cudaGetSymbolAddress((void**)&wqT, g_wqT);
    cudaGetSymbolAddress((void**)&wkT, g_wkT);
    cudaGetSymbolAddress((void**)&wvT, g_wvT);
    cudaGetSymbolAddress((void**)&woT, g_woT);
    cudaFuncSetAttribute(qkv_mma_kernel,  cudaFuncAttributeMaxDynamicSharedMemorySize, HG_SMEM_BYTES);
    cudaFuncSetAttribute(out_mma_kernel,  cudaFuncAttributeMaxDynamicSharedMemorySize, HG_SMEM_BYTES);
    cudaFuncSetAttribute(attn_mma_kernel, cudaFuncAttributeMaxDynamicSharedMemorySize, ATT_SMEM_BYTES);

    // 0) prepass
    f32_to_f16_kernel<<<(MTOT * DIM_C / 4 + 255) / 256, 256>>>(x, xh, MTOT * DIM_C / 4);
    transpose_all_kernel<<<dim3(32, 32, 4), dim3(32, 8)>>>(Wq, Wk, Wv, Wo, wqT, wkT, wvT, woT);

    // 1) QKV projection (HMMA); q pre-scaled by 0.125*log2(e)
    qkv_mma_kernel<<<dim3(12, 32), 256, HG_SMEM_BYTES>>>(xh, wqT, wkT, wvT, qhp, khp, vhp);

    // 2) flash attention (HMMA), 256-q CTAs
    attn_mma_kernel<<<dim3(SEQ / 256, NHEADS, BATCH), 512, ATT_SMEM_BYTES>>>(qhp, khp, vhp, ohp);

    // 3) output projection + bias (HMMA), fp32 out
    out_mma_kernel<<<dim3(8, 32), 256, HG_SMEM_BYTES>>>(ohp, woT, bo, out);
}